// round 14
// baseline (speedup 1.0000x reference)
#include <cuda_runtime.h>
#include <math_constants.h>

#define NPTS 4096
#define WARPS_PER_BLOCK 28
#define NTHREADS (WARPS_PER_BLOCK * 32)      // 896
#define NBLOCKS 147                           // 1 block/SM
#define FULL 0xffffffffu

__device__ __forceinline__ bool pless(float da, int ia, float db, int ib) {
    return (da < db) || (da == db && ia < ib);
}
#define CAS(dx, ix, dy, iy)                                  \
    do { if (!pless(dx, ix, dy, iy)) {                       \
        float _t = dx; dx = dy; dy = _t;                     \
        int _u = ix; ix = iy; iy = _u; } } while (0)

// private per-lane insert: strict value '<' + ascending-j within lane => exact
__device__ __forceinline__ void ins4(float dv, int j,
                                     float& d0, float& d1, float& d2, float& d3,
                                     int& i0, int& i1, int& i2, int& i3) {
    d3 = dv; i3 = j;
    if (d3 < d2) { float t=d3; d3=d2; d2=t; int u=i3; i3=i2; i2=u; }
    if (d2 < d1) { float t=d2; d2=d1; d1=t; int u=i2; i2=i1; i1=u; }
    if (d1 < d0) { float t=d1; d1=d0; d0=t; int u=i1; i1=i0; i0=u; }
}

__global__ void __launch_bounds__(NTHREADS)
nn_tag_pool_kernel(const float2* __restrict__ obs1,
                   const float2* __restrict__ obs2,
                   const float*  __restrict__ W,
                   const float*  __restrict__ bias,
                   float* __restrict__ out)
{
    __shared__ __align__(16) float sx[NPTS];
    __shared__ __align__(16) float sy[NPTS];

    const int tid = threadIdx.x;
    {   // stage + deinterleave: obs2 AoS float2 -> SoA sx/sy
        const float4* g4 = (const float4*)obs2;
        for (int m = tid; m < NPTS / 2; m += NTHREADS) {
            float4 v = g4[m];                 // {x0,y0,x1,y1}
            sx[2*m]   = v.x;  sy[2*m]   = v.y;
            sx[2*m+1] = v.z;  sy[2*m+1] = v.w;
        }
    }
    __syncthreads();

    const int warp = tid >> 5;
    const int lane = tid & 31;
    const int i = blockIdx.x * WARPS_PER_BLOCK + warp;   // query row
    if (i >= NPTS) return;                    // whole tail warps only

    const float qx = sx[i], qy = sy[i];

    const float4* sx4 = (const float4*)sx;
    const float4* sy4 = (const float4*)sy;

    // private per-lane top-4
    float d0 = CUDART_INF_F, d1 = CUDART_INF_F, d2 = CUDART_INF_F, d3 = CUDART_INF_F;
    int   i0 = 0x7fffffff,  i1 = 0x7fffffff,  i2 = 0x7fffffff,  i3 = 0x7fffffff;
    float t;                                  // warp screen threshold

    // ---------- superiter 0 = seed: unconditional private inserts, 512 pts ----
    {
        #pragma unroll
        for (int g = 0; g < 4; ++g) {
            float4 X = sx4[g * 32 + lane];
            float4 Y = sy4[g * 32 + lane];
            const int jb = g * 128 + lane * 4;
            float dxa = X.x - qx, dya = Y.x - qy;
            float dxb = X.y - qx, dyb = Y.y - qy;
            float dxc = X.z - qx, dyc = Y.z - qy;
            float dxd = X.w - qx, dyd = Y.w - qy;
            float v0 = fmaf(dxa, dxa, fmaf(dya, dya, 1.0f));
            float v1 = fmaf(dxb, dxb, fmaf(dyb, dyb, 1.0f));
            float v2 = fmaf(dxc, dxc, fmaf(dyc, dyc, 1.0f));
            float v3 = fmaf(dxd, dxd, fmaf(dyd, dyd, 1.0f));
            if (jb + 0 != i && v0 < d3) ins4(v0, jb + 0, d0,d1,d2,d3, i0,i1,i2,i3);
            if (jb + 1 != i && v1 < d3) ins4(v1, jb + 1, d0,d1,d2,d3, i0,i1,i2,i3);
            if (jb + 2 != i && v2 < d3) ins4(v2, jb + 2, d0,d1,d2,d3, i0,i1,i2,i3);
            if (jb + 3 != i && v3 < d3) ins4(v3, jb + 3, d0,d1,d2,d3, i0,i1,i2,i3);
        }
        // warp threshold: min over lanes of private 4th (>= global 4th, always)
        t = __uint_as_float(__reduce_min_sync(FULL, __float_as_uint(d3)));
    }

    // ---------- superiters 1..7: screen vs t, shfl-free private event path ----
    for (int s = 1; s < NPTS / 512; ++s) {
        const int b4 = s * 128 + lane;        // float4 base
        float v[16];
        float mg0, mg1, mg2, mg3;

        #pragma unroll
        for (int g = 0; g < 4; ++g) {
            float4 X = sx4[b4 + g * 32];
            float4 Y = sy4[b4 + g * 32];
            float dxa = X.x - qx, dya = Y.x - qy;
            float dxb = X.y - qx, dyb = Y.y - qy;
            float dxc = X.z - qx, dyc = Y.z - qy;
            float dxd = X.w - qx, dyd = Y.w - qy;
            v[g*4+0] = fmaf(dxa, dxa, fmaf(dya, dya, 1.0f));
            v[g*4+1] = fmaf(dxb, dxb, fmaf(dyb, dyb, 1.0f));
            v[g*4+2] = fmaf(dxc, dxc, fmaf(dyc, dyc, 1.0f));
            v[g*4+3] = fmaf(dxd, dxd, fmaf(dyd, dyd, 1.0f));
            float m = fminf(fminf(v[g*4+0], v[g*4+1]), fminf(v[g*4+2], v[g*4+3]));
            if (g == 0) mg0 = m; else if (g == 1) mg1 = m;
            else if (g == 2) mg2 = m; else mg3 = m;
        }
        float mall = fminf(fminf(mg0, mg1), fminf(mg2, mg3));

        // ONE ballot + uniform branch per 512 points
        if (__ballot_sync(FULL, mall <= t)) {
            const int jb = s * 512 + lane * 4; // + g*128 + h, ascending per lane
            #pragma unroll
            for (int g = 0; g < 4; ++g) {
                float mg = (g == 0) ? mg0 : (g == 1) ? mg1 : (g == 2) ? mg2 : mg3;
                if (mg <= t) {                 // per-lane, rare, NO shfls
                    #pragma unroll
                    for (int h = 0; h < 4; ++h) {
                        float dv = v[g*4+h];
                        if (dv <= t) {         // screen: t >= global 4th
                            int j = jb + g * 128 + h;
                            if (j != i && dv < d3)
                                ins4(dv, j, d0,d1,d2,d3, i0,i1,i2,i3);
                        }
                    }
                }
            }
            // tighten threshold (only on event superiters): one REDUX
            t = fminf(t, __uint_as_float(
                    __reduce_min_sync(FULL, __float_as_uint(d3))));
        }
    }

    // ---------- final indexed butterfly: 32 private sorted-4 -> top-4 --------
    #pragma unroll
    for (int off = 16; off >= 1; off >>= 1) {
        float f0 = __shfl_xor_sync(FULL, d0, off);
        float f1 = __shfl_xor_sync(FULL, d1, off);
        float f2 = __shfl_xor_sync(FULL, d2, off);
        float f3 = __shfl_xor_sync(FULL, d3, off);
        int   g0 = __shfl_xor_sync(FULL, i0, off);
        int   g1 = __shfl_xor_sync(FULL, i1, off);
        int   g2 = __shfl_xor_sync(FULL, i2, off);
        int   g3 = __shfl_xor_sync(FULL, i3, off);

        float m0, m1, m2, m3; int n0, n1, n2, n3;
        if (pless(d0, i0, f3, g3)) { m0 = d0; n0 = i0; } else { m0 = f3; n0 = g3; }
        if (pless(d1, i1, f2, g2)) { m1 = d1; n1 = i1; } else { m1 = f2; n1 = g2; }
        if (pless(d2, i2, f1, g1)) { m2 = d2; n2 = i2; } else { m2 = f1; n2 = g1; }
        if (pless(d3, i3, f0, g0)) { m3 = d3; n3 = i3; } else { m3 = f0; n3 = g0; }

        CAS(m0, n0, m2, n2); CAS(m1, n1, m3, n3);
        CAS(m0, n0, m1, n1); CAS(m2, n2, m3, n3);

        d0 = m0; d1 = m1; d2 = m2; d3 = m3;
        i0 = n0; i1 = n1; i2 = n2; i3 = n3;
    }
    // warp-uniform exact top-4 with top_k tie order

    // ---------- epilogue: lane kk*8+o -> channel o of neighbor kk ----------
    const int o = lane & 7;
    const float w0 = W[o * 6 + 0];
    const float w1 = W[o * 6 + 1];
    const float w3 = W[o * 6 + 3];
    const float w4 = W[o * 6 + 4];
    const float cb = W[o * 6 + 2] + W[o * 6 + 5] + bias[o];

    const int kk = lane >> 3;
    const int j = (kk == 0) ? i0 : (kk == 1) ? i1 : (kk == 2) ? i2 : i3;

    const float pjx = sx[j], pjy = sy[j];
    const float2 a1j = obs1[j];
    const float2 a1i = obs1[i];

    const float px = pjx - qx;
    const float py = pjy - qy;
    const float vx = (pjx - a1j.x) - (qx - a1i.x);   // vel[j] - vel[i]
    const float vy = (pjy - a1j.y) - (qy - a1i.y);

    float r = fmaf(px, w0, fmaf(py, w1, fmaf(vx, w3, fmaf(vy, w4, cb))));
    out[i * 32 + lane] = fmaxf(r, 0.0f);
}

extern "C" void kernel_launch(void* const* d_in, const int* in_sizes, int n_in,
                              void* d_out, int out_size) {
    const float2* obs1 = (const float2*)d_in[0];
    const float2* obs2 = (const float2*)d_in[1];
    const float*  Wp   = (const float*)d_in[2];
    const float*  bias = (const float*)d_in[3];
    float* out = (float*)d_out;

    nn_tag_pool_kernel<<<NBLOCKS, NTHREADS>>>(obs1, obs2, Wp, bias, out);
}

// round 15
// speedup vs baseline: 1.1216x; 1.1216x over previous
#include <cuda_runtime.h>
#include <math_constants.h>

#define NPTS 4096
#define SEEDN 512
#define WARPS_PER_BLOCK 28
#define NTHREADS (WARPS_PER_BLOCK * 32)      // 896
#define NBLOCKS 147                           // 1 block/SM
#define FULL 0xffffffffu

__device__ __forceinline__ bool pless(float da, int ia, float db, int ib) {
    return (da < db) || (da == db && ia < ib);
}
#define CAS(dx, ix, dy, iy)                                  \
    do { if (!pless(dx, ix, dy, iy)) {                       \
        float _t = dx; dx = dy; dy = _t;                     \
        int _u = ix; ix = iy; iy = _u; } } while (0)

__device__ __forceinline__ void ins4(float dv, int j,
                                     float& d0, float& d1, float& d2, float& d3,
                                     int& i0, int& i1, int& i2, int& i3) {
    // ascending j + strict '<' => exact top_k tie order
    d3 = dv; i3 = j;
    if (d3 < d2) { float t=d3; d3=d2; d2=t; int u=i3; i3=i2; i2=u; }
    if (d2 < d1) { float t=d2; d2=d1; d1=t; int u=i2; i2=i1; i1=u; }
    if (d1 < d0) { float t=d1; d1=d0; d0=t; int u=i1; i1=i0; i0=u; }
}

__global__ void __launch_bounds__(NTHREADS)
nn_tag_pool_kernel(const float2* __restrict__ obs1,
                   const float2* __restrict__ obs2,
                   const float*  __restrict__ W,
                   const float*  __restrict__ bias,
                   float* __restrict__ out)
{
    __shared__ __align__(16) float sx[NPTS];
    __shared__ __align__(16) float sy[NPTS];
    __shared__ __align__(16) float sn[NPTS];   // |p|^2

    const int tid = threadIdx.x;
    {   // stage: deinterleave + norms
        const float4* g4 = (const float4*)obs2;
        float2* sx2 = (float2*)sx;
        float2* sy2 = (float2*)sy;
        float2* sn2 = (float2*)sn;
        for (int m = tid; m < NPTS / 2; m += NTHREADS) {
            float4 v = g4[m];                  // {x0,y0,x1,y1}
            sx2[m] = make_float2(v.x, v.z);
            sy2[m] = make_float2(v.y, v.w);
            sn2[m] = make_float2(fmaf(v.x, v.x, v.y * v.y),
                                 fmaf(v.z, v.z, v.w * v.w));
        }
    }
    __syncthreads();

    const int warp = tid >> 5;
    const int lane = tid & 31;
    const int i = blockIdx.x * WARPS_PER_BLOCK + warp;
    if (i >= NPTS) return;

    const float qx = sx[i], qy = sy[i];
    const float ax = -2.0f * qx, ay = -2.0f * qy;

    const float4* sx4 = (const float4*)sx;
    const float4* sy4 = (const float4*)sy;
    const float4* sn4 = (const float4*)sn;

    // selection value: d'' = n - 2 q.p = |p-q|^2 - |q|^2 (order == true dist)
    #define DVAL(X, Y, N) fmaf((X), ax, fmaf((Y), ay, (N)))

    // ---------- seed: private top-4 over 16 pts of [0,512), then butterfly ----
    float d0 = CUDART_INF_F, d1 = CUDART_INF_F, d2 = CUDART_INF_F, d3 = CUDART_INF_F;
    int   i0 = 0x7fffffff,  i1 = 0x7fffffff,  i2 = 0x7fffffff,  i3 = 0x7fffffff;

    #pragma unroll
    for (int g = 0; g < 4; ++g) {
        float4 X = sx4[g * 32 + lane];
        float4 Y = sy4[g * 32 + lane];
        float4 N = sn4[g * 32 + lane];
        const int jb = (g * 32 + lane) * 4;
        float v0 = DVAL(X.x, Y.x, N.x);
        float v1 = DVAL(X.y, Y.y, N.y);
        float v2 = DVAL(X.z, Y.z, N.z);
        float v3 = DVAL(X.w, Y.w, N.w);
        if (jb + 0 != i && v0 < d3) ins4(v0, jb + 0, d0,d1,d2,d3, i0,i1,i2,i3);
        if (jb + 1 != i && v1 < d3) ins4(v1, jb + 1, d0,d1,d2,d3, i0,i1,i2,i3);
        if (jb + 2 != i && v2 < d3) ins4(v2, jb + 2, d0,d1,d2,d3, i0,i1,i2,i3);
        if (jb + 3 != i && v3 < d3) ins4(v3, jb + 3, d0,d1,d2,d3, i0,i1,i2,i3);
    }

    #pragma unroll
    for (int off = 16; off >= 1; off >>= 1) {   // indexed butterfly -> uniform
        float f0 = __shfl_xor_sync(FULL, d0, off);
        float f1 = __shfl_xor_sync(FULL, d1, off);
        float f2 = __shfl_xor_sync(FULL, d2, off);
        float f3 = __shfl_xor_sync(FULL, d3, off);
        int   g0 = __shfl_xor_sync(FULL, i0, off);
        int   g1 = __shfl_xor_sync(FULL, i1, off);
        int   g2 = __shfl_xor_sync(FULL, i2, off);
        int   g3 = __shfl_xor_sync(FULL, i3, off);

        float m0, m1, m2, m3; int n0, n1, n2, n3;
        if (pless(d0, i0, f3, g3)) { m0 = d0; n0 = i0; } else { m0 = f3; n0 = g3; }
        if (pless(d1, i1, f2, g2)) { m1 = d1; n1 = i1; } else { m1 = f2; n1 = g2; }
        if (pless(d2, i2, f1, g1)) { m2 = d2; n2 = i2; } else { m2 = f1; n2 = g1; }
        if (pless(d3, i3, f0, g0)) { m3 = d3; n3 = i3; } else { m3 = f0; n3 = g0; }

        CAS(m0, n0, m2, n2); CAS(m1, n1, m3, n3);
        CAS(m0, n0, m1, n1); CAS(m2, n2, m3, n3);

        d0 = m0; d1 = m1; d2 = m2; d3 = m3;
        i0 = n0; i1 = n1; i2 = n2; i3 = n3;
    }
    // warp-uniform exact top-4 of [0,512); d3 = tight threshold

    // ---------- main scan: [512,4096), 14 superiters of 256 points ----------
    #pragma unroll 2
    for (int s = 0; s < (NPTS - SEEDN) / 256; ++s) {
        const int b4 = (SEEDN / 4) + s * 64 + lane;
        float4 XA = sx4[b4],      YA = sy4[b4],      NA = sn4[b4];
        float4 XB = sx4[b4 + 32], YB = sy4[b4 + 32], NB = sn4[b4 + 32];

        float va0 = DVAL(XA.x, YA.x, NA.x);
        float va1 = DVAL(XA.y, YA.y, NA.y);
        float va2 = DVAL(XA.z, YA.z, NA.z);
        float va3 = DVAL(XA.w, YA.w, NA.w);
        float vb0 = DVAL(XB.x, YB.x, NB.x);
        float vb1 = DVAL(XB.y, YB.y, NB.y);
        float vb2 = DVAL(XB.z, YB.z, NB.z);
        float vb3 = DVAL(XB.w, YB.w, NB.w);

        float mga = fminf(fminf(va0, va1), fminf(va2, va3));
        float mgb = fminf(fminf(vb0, vb1), fminf(vb2, vb3));

        // ONE ballot + uniform branch per 256 points
        if (__ballot_sync(FULL, fminf(mga, mgb) < d3)) {
            // group A: points SEEDN + s*256 + [0,128)
            unsigned mk = __ballot_sync(FULL, mga < d3);
            while (mk) {                       // warp-uniform
                int r = __ffs(mk) - 1;
                mk &= mk - 1;
                float x0 = __shfl_sync(FULL, va0, r);
                float x1 = __shfl_sync(FULL, va1, r);
                float x2 = __shfl_sync(FULL, va2, r);
                float x3 = __shfl_sync(FULL, va3, r);
                int jb = SEEDN + s * 256 + 4 * r;
                if (jb + 0 != i && x0 < d3) ins4(x0, jb + 0, d0,d1,d2,d3, i0,i1,i2,i3);
                if (jb + 1 != i && x1 < d3) ins4(x1, jb + 1, d0,d1,d2,d3, i0,i1,i2,i3);
                if (jb + 2 != i && x2 < d3) ins4(x2, jb + 2, d0,d1,d2,d3, i0,i1,i2,i3);
                if (jb + 3 != i && x3 < d3) ins4(x3, jb + 3, d0,d1,d2,d3, i0,i1,i2,i3);
                if (mk) mk &= __ballot_sync(FULL, mga < d3);
            }
            // group B: points SEEDN + s*256 + [128,256)
            mk = __ballot_sync(FULL, mgb < d3);
            while (mk) {
                int r = __ffs(mk) - 1;
                mk &= mk - 1;
                float x0 = __shfl_sync(FULL, vb0, r);
                float x1 = __shfl_sync(FULL, vb1, r);
                float x2 = __shfl_sync(FULL, vb2, r);
                float x3 = __shfl_sync(FULL, vb3, r);
                int jb = SEEDN + s * 256 + 128 + 4 * r;
                if (jb + 0 != i && x0 < d3) ins4(x0, jb + 0, d0,d1,d2,d3, i0,i1,i2,i3);
                if (jb + 1 != i && x1 < d3) ins4(x1, jb + 1, d0,d1,d2,d3, i0,i1,i2,i3);
                if (jb + 2 != i && x2 < d3) ins4(x2, jb + 2, d0,d1,d2,d3, i0,i1,i2,i3);
                if (jb + 3 != i && x3 < d3) ins4(x3, jb + 3, d0,d1,d2,d3, i0,i1,i2,i3);
                if (mk) mk &= __ballot_sync(FULL, mgb < d3);
            }
        }
    }

    // ---------- epilogue: list warp-uniform; lane kk*8+o -> channel o --------
    const int o = lane & 7;
    const float w0 = W[o * 6 + 0];
    const float w1 = W[o * 6 + 1];
    const float w3 = W[o * 6 + 3];
    const float w4 = W[o * 6 + 4];
    const float cb = W[o * 6 + 2] + W[o * 6 + 5] + bias[o];

    const int kk = lane >> 3;
    const int j = (kk == 0) ? i0 : (kk == 1) ? i1 : (kk == 2) ? i2 : i3;

    const float pjx = sx[j], pjy = sy[j];
    const float2 a1j = obs1[j];
    const float2 a1i = obs1[i];

    const float px = pjx - qx;
    const float py = pjy - qy;
    const float vx = (pjx - a1j.x) - (qx - a1i.x);   // vel[j] - vel[i]
    const float vy = (pjy - a1j.y) - (qy - a1i.y);

    float r = fmaf(px, w0, fmaf(py, w1, fmaf(vx, w3, fmaf(vy, w4, cb))));
    out[i * 32 + lane] = fmaxf(r, 0.0f);
}

extern "C" void kernel_launch(void* const* d_in, const int* in_sizes, int n_in,
                              void* d_out, int out_size) {
    const float2* obs1 = (const float2*)d_in[0];
    const float2* obs2 = (const float2*)d_in[1];
    const float*  Wp   = (const float*)d_in[2];
    const float*  bias = (const float*)d_in[3];
    float* out = (float*)d_out;

    nn_tag_pool_kernel<<<NBLOCKS, NTHREADS>>>(obs1, obs2, Wp, bias, out);
}